// round 12
// baseline (speedup 1.0000x reference)
#include <cuda_runtime.h>
#include <math.h>

#define TPB 256
#define NBATCH 16
#define NBOX 64
#define NCLS 30

// softplus blocks: each handles 512 float4 (2048 floats)
#define SP0_BLOCKS 50
#define SP1_BLOCKS 13
#define SP2_BLOCKS 4
#define SP_BLOCKS (SP0_BLOCKS + SP1_BLOCKS + SP2_BLOCKS)   // 67
#define AS_BLOCKS 48                                        // 3 scales * 16 batches
#define TOTAL_BLOCKS (SP_BLOCKS + AS_BLOCKS)                // 115

__device__ float  g_blk_sp[SP_BLOCKS];
__device__ float4 g_blk_as[AS_BLOCKS];     // {cls_sum, reg_sum, obj_pos_sum, npos}
__device__ unsigned int g_done = 0;

static __device__ __forceinline__ float softplus_f(float x) {
    return fmaxf(x, 0.0f) + __logf(1.0f + __expf(-fabsf(x)));
}

// block reduce; result valid on thread 0
static __device__ __forceinline__ float blk_reduce(float v) {
    __shared__ float sh[TPB / 32];
    __syncthreads();
    #pragma unroll
    for (int o = 16; o > 0; o >>= 1) v += __shfl_down_sync(0xffffffffu, v, o);
    int lane = threadIdx.x & 31, w = threadIdx.x >> 5;
    if (lane == 0) sh[w] = v;
    __syncthreads();
    v = (threadIdx.x < TPB / 32) ? sh[threadIdx.x] : 0.0f;
    if (w == 0) {
        #pragma unroll
        for (int o = TPB / 64; o > 0; o >>= 1) v += __shfl_down_sync(0xffffffffu, v, o);
    }
    return v;
}

__global__ __launch_bounds__(TPB)
void detloss_kernel(const float* __restrict__ cls0, const float* __restrict__ cls1,
                    const float* __restrict__ cls2,
                    const float* __restrict__ reg0, const float* __restrict__ reg1,
                    const float* __restrict__ reg2,
                    const float* __restrict__ obj0, const float* __restrict__ obj1,
                    const float* __restrict__ obj2,
                    const float* __restrict__ boxes, const int* __restrict__ labels,
                    float* __restrict__ out)
{
    const float* clsp[3] = {cls0, cls1, cls2};
    const float* regp[3] = {reg0, reg1, reg2};
    const float* objp[3] = {obj0, obj1, obj2};

    int bid = blockIdx.x;
    int t = threadIdx.x;

    if (bid < SP_BLOCKS) {
        // ---- objectness softplus sum: 2 float4 per thread ----
        const float4* src;
        int base, lim;
        if (bid < SP0_BLOCKS) {
            src = (const float4*)obj0; base = bid * 512; lim = 25600;
        } else if (bid < SP0_BLOCKS + SP1_BLOCKS) {
            src = (const float4*)obj1; base = (bid - SP0_BLOCKS) * 512; lim = 6400;
        } else {
            src = (const float4*)obj2; base = (bid - SP0_BLOCKS - SP1_BLOCKS) * 512; lim = 1600;
        }
        int i0 = base + t, i1 = base + 256 + t;
        float acc = 0.0f;
        if (i0 < lim) {
            float4 v = src[i0];
            acc += softplus_f(v.x) + softplus_f(v.y) + softplus_f(v.z) + softplus_f(v.w);
        }
        if (i1 < lim) {
            float4 v = src[i1];
            acc += softplus_f(v.x) + softplus_f(v.y) + softplus_f(v.z) + softplus_f(v.w);
        }
        float tot = blk_reduce(acc);
        if (t == 0) __stcg(&g_blk_sp[bid], tot);
    } else {
        // ---- per (scale, batch): 4 threads per box ----
        int idx = bid - SP_BLOCKS;
        int s = idx >> 4;          // 0..2
        int b = idx & 15;          // 0..15
        int Wd = 80 >> s;          // 80, 40, 20
        int HW = Wd * Wd;

        int box  = t >> 2;         // 0..63
        int part = t & 3;          // 0..3

        __shared__ int spk[NBOX];       // packed (cell<<5)|label
        __shared__ float4 wsum[TPB/32]; // per-warp partial sums

        // box coords + cell (all 4 parts compute identically; broadcast loads)
        const float4 bx = ((const float4*)boxes)[b * NBOX + box];
        int gx = (int)(bx.x * (float)Wd);
        int gy = (int)(bx.y * (float)Wd);
        gx = max(0, min(gx, Wd - 1));
        gy = max(0, min(gy, Wd - 1));
        int cell = gy * Wd + gx;
        int lab  = labels[b * NBOX + box];
        int mypk = (cell << 5) | lab;
        if (part == 0) spk[box] = mypk;

        // ---- speculative gathers (issued before the barrier; scattered) ----
        // classes: part p covers [8p, 8p+8) (part 3: 6 real + 2 padded)
        int cbase = part * 8;
        const float* cp = clsp[s] + (size_t)b * NCLS * HW + cell;
        float v[8];
        #pragma unroll
        for (int i = 0; i < 8; i++) {
            int c = cbase + i;
            int cc = min(c, NCLS - 1);
            float val = __ldg(&cp[(size_t)cc * HW]);
            v[i] = (c < NCLS) ? val : -1e30f;
        }
        // reg: part p loads coordinate p
        float regv = __ldg(&regp[s][(size_t)b * 4 * HW + (size_t)part * HW + cell]);
        // obj: part 3 loads it
        float objv = (part == 3) ? __ldg(&objp[s][(size_t)b * HW + cell]) : 0.0f;
        __syncthreads();

        // ---- collision resolution: split across the 4 parts (16 boxes each) ----
        int mlpk = mypk;
        int lose = 0;
        #pragma unroll
        for (int jj = 0; jj < 16; jj++) {
            int j = part * 16 + jj;
            int pj = spk[j];
            bool eq = (((pj ^ mypk) & ~31) == 0);   // same cell
            mlpk = (eq && pj < mlpk) ? pj : mlpk;    // min packed -> min label in cell
            lose |= (eq && j > box) ? 1 : 0;         // a later box overwrites this cell
        }
        // combine partials across the 4-lane group
        mlpk = min(mlpk, __shfl_xor_sync(0xffffffffu, mlpk, 1));
        mlpk = min(mlpk, __shfl_xor_sync(0xffffffffu, mlpk, 2));
        lose |= __shfl_xor_sync(0xffffffffu, lose, 1);
        lose |= __shfl_xor_sync(0xffffffffu, lose, 2);
        int ml = mlpk & 31;
        bool winner = (lose == 0);

        // ---- group-of-4 combine (contiguous lanes, same warp) ----
        float m = v[0];
        #pragma unroll
        for (int i = 1; i < 8; i++) m = fmaxf(m, v[i]);
        m = fmaxf(m, __shfl_xor_sync(0xffffffffu, m, 1));
        m = fmaxf(m, __shfl_xor_sync(0xffffffffu, m, 2));

        float ssum = 0.0f, tgt = 0.0f;
        #pragma unroll
        for (int i = 0; i < 8; i++) {
            int c = cbase + i;
            ssum += __expf(v[i] - m);                // padded entries -> exp(-huge)=0
            tgt = (c == ml) ? v[i] : tgt;
        }
        float bc = (part == 0) ? bx.x : (part == 1) ? bx.y : (part == 2) ? bx.z : bx.w;
        float d = fabsf(regv - bc);
        float sl = (d < 1.0f) ? 0.5f * d * d : d - 0.5f;

        ssum += __shfl_xor_sync(0xffffffffu, ssum, 1);
        ssum += __shfl_xor_sync(0xffffffffu, ssum, 2);
        tgt  += __shfl_xor_sync(0xffffffffu, tgt, 1);
        tgt  += __shfl_xor_sync(0xffffffffu, tgt, 2);
        sl   += __shfl_xor_sync(0xffffffffu, sl, 1);
        sl   += __shfl_xor_sync(0xffffffffu, sl, 2);

        float cls_l = 0.0f, reg_l = 0.0f, objp_l = 0.0f, np_l = 0.0f;
        if (winner) {
            if (part == 0) {
                np_l  = 1.0f;
                cls_l = m + __logf(ssum) - tgt;
                reg_l = fminf(sl * 0.25f, 10.0f);
            }
            if (part == 3) objp_l = objv;
        }

        // ---- lean block reduce: warp reduce -> 1 barrier -> warp 0 finish ----
        #pragma unroll
        for (int o = 16; o > 0; o >>= 1) {
            cls_l  += __shfl_xor_sync(0xffffffffu, cls_l,  o);
            reg_l  += __shfl_xor_sync(0xffffffffu, reg_l,  o);
            objp_l += __shfl_xor_sync(0xffffffffu, objp_l, o);
            np_l   += __shfl_xor_sync(0xffffffffu, np_l,   o);
        }
        int lane = t & 31, w = t >> 5;
        if (lane == 0) wsum[w] = make_float4(cls_l, reg_l, objp_l, np_l);
        __syncthreads();
        if (w == 0) {
            float4 a = (lane < TPB / 32) ? wsum[lane] : make_float4(0.f, 0.f, 0.f, 0.f);
            #pragma unroll
            for (int o = 4; o > 0; o >>= 1) {
                a.x += __shfl_xor_sync(0xffffffffu, a.x, o);
                a.y += __shfl_xor_sync(0xffffffffu, a.y, o);
                a.z += __shfl_xor_sync(0xffffffffu, a.z, o);
                a.w += __shfl_xor_sync(0xffffffffu, a.w, o);
            }
            if (lane == 0) __stcg(&g_blk_as[idx], a);
        }
    }

    // ---- last arriving block: single acq_rel ticket ----
    __shared__ bool amLast;
    if (t == 0) {
        unsigned vv;
        asm volatile("atom.add.acq_rel.gpu.global.u32 %0, [%1], %2;"
                     : "=r"(vv) : "l"(&g_done), "r"(1u) : "memory");
        amLast = (vv == (unsigned)(gridDim.x - 1));
    }
    __syncthreads();
    if (!amLast) return;

    // ---- fast tail: single warp-parallel pass, one barrier ----
    int lane = t & 31, w = t >> 5;
    __shared__ float fin[6][4];   // [0..2]: asgn per scale {cls,reg,objp,npos}; [3..5]: sp sums {s0,s1,s2,-}

    if (w < 3) {
        // warp w reduces the 16 assignment partials of scale w
        float4 a4 = make_float4(0.f, 0.f, 0.f, 0.f);
        if (lane < NBATCH) a4 = __ldcg(&g_blk_as[w * NBATCH + lane]);
        #pragma unroll
        for (int o = 8; o > 0; o >>= 1) {
            a4.x += __shfl_xor_sync(0xffffffffu, a4.x, o);
            a4.y += __shfl_xor_sync(0xffffffffu, a4.y, o);
            a4.z += __shfl_xor_sync(0xffffffffu, a4.z, o);
            a4.w += __shfl_xor_sync(0xffffffffu, a4.w, o);
        }
        if (lane == 0) { fin[w][0] = a4.x; fin[w][1] = a4.y; fin[w][2] = a4.z; fin[w][3] = a4.w; }
    } else if (w < 6) {
        // warps 3..5 reduce the 67 softplus partials, masked into 3 per-scale sums
        int i = (w - 3) * 32 + lane;
        float pv = (i < SP_BLOCKS) ? __ldcg(&g_blk_sp[i]) : 0.0f;
        float l0 = (i < SP0_BLOCKS) ? pv : 0.0f;
        float l1 = (i >= SP0_BLOCKS && i < SP0_BLOCKS + SP1_BLOCKS) ? pv : 0.0f;
        float l2 = (i >= SP0_BLOCKS + SP1_BLOCKS && i < SP_BLOCKS) ? pv : 0.0f;
        #pragma unroll
        for (int o = 16; o > 0; o >>= 1) {
            l0 += __shfl_xor_sync(0xffffffffu, l0, o);
            l1 += __shfl_xor_sync(0xffffffffu, l1, o);
            l2 += __shfl_xor_sync(0xffffffffu, l2, o);
        }
        if (lane == 0) { fin[w][0] = l0; fin[w][1] = l1; fin[w][2] = l2; fin[w][3] = 0.0f; }
    }
    __syncthreads();

    if (t == 0) {
        float cls_tot = 0.0f, reg_tot = 0.0f, obj_tot = 0.0f;
        #pragma unroll
        for (int s = 0; s < 3; s++) {
            float sp_s = fin[3][s] + fin[4][s] + fin[5][s];
            float npos = fmaxf(fin[s][3], 1.0f);
            int Wd = 80 >> s;
            float Ms = (float)(NBATCH * Wd * Wd);
            cls_tot += fin[s][0] / npos;               // CLS_W = 1
            reg_tot += fin[s][1] / npos * 5.0f;        // REG_W = 5
            obj_tot += (sp_s - fin[s][2]) / Ms;        // OBJ_W = 1
        }
        cls_tot *= (1.0f / 3.0f);
        reg_tot *= (1.0f / 3.0f);
        obj_tot *= (1.0f / 3.0f);
        float4 o4 = make_float4(cls_tot + reg_tot + obj_tot, cls_tot, reg_tot, obj_tot);
        *(float4*)out = o4;
        g_done = 0;   // reset for next graph replay
    }
}

extern "C" void kernel_launch(void* const* d_in, const int* in_sizes, int n_in,
                              void* d_out, int out_size)
{
    const float *cls[3], *reg[3], *obj[3];
    if (in_sizes[1] == 409600) {   // dict order: cls0,reg0,obj0,cls1,...
        cls[0] = (const float*)d_in[0]; reg[0] = (const float*)d_in[1]; obj[0] = (const float*)d_in[2];
        cls[1] = (const float*)d_in[3]; reg[1] = (const float*)d_in[4]; obj[1] = (const float*)d_in[5];
        cls[2] = (const float*)d_in[6]; reg[2] = (const float*)d_in[7]; obj[2] = (const float*)d_in[8];
    } else {                        // signature order: cls0,cls1,cls2,reg0,...
        cls[0] = (const float*)d_in[0]; cls[1] = (const float*)d_in[1]; cls[2] = (const float*)d_in[2];
        reg[0] = (const float*)d_in[3]; reg[1] = (const float*)d_in[4]; reg[2] = (const float*)d_in[5];
        obj[0] = (const float*)d_in[6]; obj[1] = (const float*)d_in[7]; obj[2] = (const float*)d_in[8];
    }
    const float* boxes  = (const float*)d_in[9];
    const int*   labels = (const int*)d_in[10];
    float* out = (float*)d_out;

    detloss_kernel<<<TOTAL_BLOCKS, TPB>>>(
        cls[0], cls[1], cls[2],
        reg[0], reg[1], reg[2],
        obj[0], obj[1], obj[2],
        boxes, labels, out);
}

// round 13
// speedup vs baseline: 1.1905x; 1.1905x over previous
#include <cuda_runtime.h>
#include <math.h>

#define TPB 256
#define NBATCH 16
#define NBOX 64
#define NCLS 30

// softplus blocks: each handles 512 float4 (2048 floats)
#define SP0_BLOCKS 50
#define SP1_BLOCKS 13
#define SP2_BLOCKS 4
#define SP_BLOCKS (SP0_BLOCKS + SP1_BLOCKS + SP2_BLOCKS)   // 67
#define AS_BLOCKS 48                                        // 3 scales * 16 batches
#define TOTAL_BLOCKS (SP_BLOCKS + AS_BLOCKS)                // 115

__device__ float  g_blk_sp[SP_BLOCKS];
__device__ float4 g_blk_as[AS_BLOCKS];     // {cls_sum, reg_sum, obj_pos_sum, npos}
__device__ unsigned int g_done = 0;

static __device__ __forceinline__ float softplus_f(float x) {
    return fmaxf(x, 0.0f) + __logf(1.0f + __expf(-fabsf(x)));
}

// block reduce; result valid on thread 0
static __device__ __forceinline__ float blk_reduce(float v) {
    __shared__ float sh[TPB / 32];
    __syncthreads();
    #pragma unroll
    for (int o = 16; o > 0; o >>= 1) v += __shfl_down_sync(0xffffffffu, v, o);
    int lane = threadIdx.x & 31, w = threadIdx.x >> 5;
    if (lane == 0) sh[w] = v;
    __syncthreads();
    v = (threadIdx.x < TPB / 32) ? sh[threadIdx.x] : 0.0f;
    if (w == 0) {
        #pragma unroll
        for (int o = TPB / 64; o > 0; o >>= 1) v += __shfl_down_sync(0xffffffffu, v, o);
    }
    return v;
}

// fused 4-value block reduce (2 barriers); results valid on thread 0 in r[0..3]
static __device__ __forceinline__ void blk_reduce4(float v0, float v1, float v2, float v3,
                                                   float* r) {
    __shared__ float sh[TPB / 32][4];
    __syncthreads();
    #pragma unroll
    for (int o = 16; o > 0; o >>= 1) {
        v0 += __shfl_xor_sync(0xffffffffu, v0, o);
        v1 += __shfl_xor_sync(0xffffffffu, v1, o);
        v2 += __shfl_xor_sync(0xffffffffu, v2, o);
        v3 += __shfl_xor_sync(0xffffffffu, v3, o);
    }
    int lane = threadIdx.x & 31, w = threadIdx.x >> 5;
    if (lane == 0) { sh[w][0] = v0; sh[w][1] = v1; sh[w][2] = v2; sh[w][3] = v3; }
    __syncthreads();
    if (threadIdx.x == 0) {
        float a = 0.f, b = 0.f, c = 0.f, d = 0.f;
        #pragma unroll
        for (int i = 0; i < TPB / 32; i++) {
            a += sh[i][0]; b += sh[i][1]; c += sh[i][2]; d += sh[i][3];
        }
        r[0] = a; r[1] = b; r[2] = c; r[3] = d;
    }
}

__global__ __launch_bounds__(TPB)
void detloss_kernel(const float* __restrict__ cls0, const float* __restrict__ cls1,
                    const float* __restrict__ cls2,
                    const float* __restrict__ reg0, const float* __restrict__ reg1,
                    const float* __restrict__ reg2,
                    const float* __restrict__ obj0, const float* __restrict__ obj1,
                    const float* __restrict__ obj2,
                    const float* __restrict__ boxes, const int* __restrict__ labels,
                    float* __restrict__ out)
{
    const float* clsp[3] = {cls0, cls1, cls2};
    const float* regp[3] = {reg0, reg1, reg2};
    const float* objp[3] = {obj0, obj1, obj2};

    int bid = blockIdx.x;
    int t = threadIdx.x;

    if (bid < SP_BLOCKS) {
        // ---- objectness softplus sum: 2 float4 per thread ----
        const float4* src;
        int base, lim;
        if (bid < SP0_BLOCKS) {
            src = (const float4*)obj0; base = bid * 512; lim = 25600;
        } else if (bid < SP0_BLOCKS + SP1_BLOCKS) {
            src = (const float4*)obj1; base = (bid - SP0_BLOCKS) * 512; lim = 6400;
        } else {
            src = (const float4*)obj2; base = (bid - SP0_BLOCKS - SP1_BLOCKS) * 512; lim = 1600;
        }
        int i0 = base + t, i1 = base + 256 + t;
        float acc = 0.0f;
        if (i0 < lim) {
            float4 v = src[i0];
            acc += softplus_f(v.x) + softplus_f(v.y) + softplus_f(v.z) + softplus_f(v.w);
        }
        if (i1 < lim) {
            float4 v = src[i1];
            acc += softplus_f(v.x) + softplus_f(v.y) + softplus_f(v.z) + softplus_f(v.w);
        }
        float tot = blk_reduce(acc);
        if (t == 0) __stcg(&g_blk_sp[bid], tot);
    } else {
        // ---- per (scale, batch): 4 threads per box ----
        int idx = bid - SP_BLOCKS;
        int s = idx >> 4;          // 0..2
        int b = idx & 15;          // 0..15
        int Wd = 80 >> s;          // 80, 40, 20
        int HW = Wd * Wd;

        int box  = t >> 2;         // 0..63
        int part = t & 3;          // 0..3

        __shared__ int spk[NBOX];  // packed (cell<<5)|label

        // box coords + cell (all 4 parts compute identically; broadcast loads)
        const float4 bx = ((const float4*)boxes)[b * NBOX + box];
        int gx = (int)(bx.x * (float)Wd);
        int gy = (int)(bx.y * (float)Wd);
        gx = max(0, min(gx, Wd - 1));
        gy = max(0, min(gy, Wd - 1));
        int cell = gy * Wd + gx;
        int lab  = labels[b * NBOX + box];
        int mypk = (cell << 5) | lab;
        if (part == 0) spk[box] = mypk;

        // ---- speculative gathers (issued before the barrier; scattered) ----
        // classes: part p covers [8p, 8p+8) (part 3: 6 real + 2 padded)
        int cbase = part * 8;
        const float* cp = clsp[s] + (size_t)b * NCLS * HW + cell;
        float v[8];
        #pragma unroll
        for (int i = 0; i < 8; i++) {
            int c = cbase + i;
            int cc = min(c, NCLS - 1);
            float val = __ldg(&cp[(size_t)cc * HW]);
            v[i] = (c < NCLS) ? val : -1e30f;
        }
        // reg: part p loads coordinate p
        float regv = __ldg(&regp[s][(size_t)b * 4 * HW + (size_t)part * HW + cell]);
        // obj: part 3 loads it
        float objv = (part == 3) ? __ldg(&objp[s][(size_t)b * HW + cell]) : 0.0f;
        __syncthreads();

        // ---- collision resolution: split across the 4 parts (16 boxes each) ----
        int mlpk = mypk;
        int lose = 0;
        #pragma unroll
        for (int jj = 0; jj < 16; jj++) {
            int j = part * 16 + jj;
            int pj = spk[j];
            bool eq = (((pj ^ mypk) & ~31) == 0);   // same cell
            mlpk = (eq && pj < mlpk) ? pj : mlpk;    // min packed -> min label in cell
            lose |= (eq && j > box) ? 1 : 0;         // a later box overwrites this cell
        }
        // combine partials across the 4-lane group
        mlpk = min(mlpk, __shfl_xor_sync(0xffffffffu, mlpk, 1));
        mlpk = min(mlpk, __shfl_xor_sync(0xffffffffu, mlpk, 2));
        lose |= __shfl_xor_sync(0xffffffffu, lose, 1);
        lose |= __shfl_xor_sync(0xffffffffu, lose, 2);
        int ml = mlpk & 31;
        bool winner = (lose == 0);

        // ---- group-of-4 combine (contiguous lanes, same warp) ----
        float m = v[0];
        #pragma unroll
        for (int i = 1; i < 8; i++) m = fmaxf(m, v[i]);
        m = fmaxf(m, __shfl_xor_sync(0xffffffffu, m, 1));
        m = fmaxf(m, __shfl_xor_sync(0xffffffffu, m, 2));

        float ssum = 0.0f, tgt = 0.0f;
        #pragma unroll
        for (int i = 0; i < 8; i++) {
            int c = cbase + i;
            ssum += __expf(v[i] - m);                // padded entries -> exp(-huge)=0
            tgt = (c == ml) ? v[i] : tgt;
        }
        float bc = (part == 0) ? bx.x : (part == 1) ? bx.y : (part == 2) ? bx.z : bx.w;
        float d = fabsf(regv - bc);
        float sl = (d < 1.0f) ? 0.5f * d * d : d - 0.5f;

        ssum += __shfl_xor_sync(0xffffffffu, ssum, 1);
        ssum += __shfl_xor_sync(0xffffffffu, ssum, 2);
        tgt  += __shfl_xor_sync(0xffffffffu, tgt, 1);
        tgt  += __shfl_xor_sync(0xffffffffu, tgt, 2);
        sl   += __shfl_xor_sync(0xffffffffu, sl, 1);
        sl   += __shfl_xor_sync(0xffffffffu, sl, 2);

        float cls_l = 0.0f, reg_l = 0.0f, objp_l = 0.0f, np_l = 0.0f;
        if (winner) {
            if (part == 0) {
                np_l  = 1.0f;
                cls_l = m + __logf(ssum) - tgt;
                reg_l = fminf(sl * 0.25f, 10.0f);
            }
            if (part == 3) objp_l = objv;
        }
        __shared__ float res[4];
        blk_reduce4(cls_l, reg_l, objp_l, np_l, res);
        if (t == 0) {
            float4 o4 = make_float4(res[0], res[1], res[2], res[3]);
            __stcg(&g_blk_as[idx], o4);
        }
    }

    // ---- last arriving block: single acq_rel ticket ----
    __shared__ bool amLast;
    if (t == 0) {
        unsigned vv;
        asm volatile("atom.add.acq_rel.gpu.global.u32 %0, [%1], %2;"
                     : "=r"(vv) : "l"(&g_done), "r"(1u) : "memory");
        amLast = (vv == (unsigned)(gridDim.x - 1));
    }
    __syncthreads();
    if (!amLast) return;

    // ---- fast tail: single warp-parallel pass, one barrier ----
    int lane = t & 31, w = t >> 5;
    __shared__ float fin[6][4];   // [0..2]: asgn per scale {cls,reg,objp,npos}; [3..5]: sp sums {s0,s1,s2,-}

    if (w < 3) {
        // warp w reduces the 16 assignment partials of scale w
        float4 a4 = make_float4(0.f, 0.f, 0.f, 0.f);
        if (lane < NBATCH) a4 = __ldcg(&g_blk_as[w * NBATCH + lane]);
        #pragma unroll
        for (int o = 8; o > 0; o >>= 1) {
            a4.x += __shfl_xor_sync(0xffffffffu, a4.x, o);
            a4.y += __shfl_xor_sync(0xffffffffu, a4.y, o);
            a4.z += __shfl_xor_sync(0xffffffffu, a4.z, o);
            a4.w += __shfl_xor_sync(0xffffffffu, a4.w, o);
        }
        if (lane == 0) { fin[w][0] = a4.x; fin[w][1] = a4.y; fin[w][2] = a4.z; fin[w][3] = a4.w; }
    } else if (w < 6) {
        // warps 3..5 reduce the 67 softplus partials, masked into 3 per-scale sums
        int i = (w - 3) * 32 + lane;
        float pv = (i < SP_BLOCKS) ? __ldcg(&g_blk_sp[i]) : 0.0f;
        float l0 = (i < SP0_BLOCKS) ? pv : 0.0f;
        float l1 = (i >= SP0_BLOCKS && i < SP0_BLOCKS + SP1_BLOCKS) ? pv : 0.0f;
        float l2 = (i >= SP0_BLOCKS + SP1_BLOCKS && i < SP_BLOCKS) ? pv : 0.0f;
        #pragma unroll
        for (int o = 16; o > 0; o >>= 1) {
            l0 += __shfl_xor_sync(0xffffffffu, l0, o);
            l1 += __shfl_xor_sync(0xffffffffu, l1, o);
            l2 += __shfl_xor_sync(0xffffffffu, l2, o);
        }
        if (lane == 0) { fin[w][0] = l0; fin[w][1] = l1; fin[w][2] = l2; fin[w][3] = 0.0f; }
    }
    __syncthreads();

    if (t == 0) {
        float cls_tot = 0.0f, reg_tot = 0.0f, obj_tot = 0.0f;
        #pragma unroll
        for (int s = 0; s < 3; s++) {
            float sp_s = fin[3][s] + fin[4][s] + fin[5][s];
            float npos = fmaxf(fin[s][3], 1.0f);
            int Wd = 80 >> s;
            float Ms = (float)(NBATCH * Wd * Wd);
            cls_tot += fin[s][0] / npos;               // CLS_W = 1
            reg_tot += fin[s][1] / npos * 5.0f;        // REG_W = 5
            obj_tot += (sp_s - fin[s][2]) / Ms;        // OBJ_W = 1
        }
        cls_tot *= (1.0f / 3.0f);
        reg_tot *= (1.0f / 3.0f);
        obj_tot *= (1.0f / 3.0f);
        out[0] = cls_tot + reg_tot + obj_tot;
        out[1] = cls_tot;
        out[2] = reg_tot;
        out[3] = obj_tot;
        g_done = 0;   // reset for next graph replay
    }
}

extern "C" void kernel_launch(void* const* d_in, const int* in_sizes, int n_in,
                              void* d_out, int out_size)
{
    const float *cls[3], *reg[3], *obj[3];
    if (in_sizes[1] == 409600) {   // dict order: cls0,reg0,obj0,cls1,...
        cls[0] = (const float*)d_in[0]; reg[0] = (const float*)d_in[1]; obj[0] = (const float*)d_in[2];
        cls[1] = (const float*)d_in[3]; reg[1] = (const float*)d_in[4]; obj[1] = (const float*)d_in[5];
        cls[2] = (const float*)d_in[6]; reg[2] = (const float*)d_in[7]; obj[2] = (const float*)d_in[8];
    } else {                        // signature order: cls0,cls1,cls2,reg0,...
        cls[0] = (const float*)d_in[0]; cls[1] = (const float*)d_in[1]; cls[2] = (const float*)d_in[2];
        reg[0] = (const float*)d_in[3]; reg[1] = (const float*)d_in[4]; reg[2] = (const float*)d_in[5];
        obj[0] = (const float*)d_in[6]; obj[1] = (const float*)d_in[7]; obj[2] = (const float*)d_in[8];
    }
    const float* boxes  = (const float*)d_in[9];
    const int*   labels = (const int*)d_in[10];
    float* out = (float*)d_out;

    detloss_kernel<<<TOTAL_BLOCKS, TPB>>>(
        cls[0], cls[1], cls[2],
        reg[0], reg[1], reg[2],
        obj[0], obj[1], obj[2],
        boxes, labels, out);
}

// round 14
// speedup vs baseline: 1.4815x; 1.2444x over previous
#include <cuda_runtime.h>
#include <math.h>

#define TPB 256
#define NBATCH 16
#define NBOX 64
#define NCLS 30

// softplus blocks: each handles 512 float4 (2048 floats)
#define SP0_BLOCKS 50
#define SP1_BLOCKS 13
#define SP2_BLOCKS 4
#define SP_BLOCKS (SP0_BLOCKS + SP1_BLOCKS + SP2_BLOCKS)   // 67
#define AS_BLOCKS 48                                        // 3 scales * 16 batches
#define TOTAL_BLOCKS (SP_BLOCKS + AS_BLOCKS)                // 115

__device__ float  g_blk_sp[SP_BLOCKS];
__device__ float4 g_blk_as[AS_BLOCKS];     // {cls_sum, reg_sum, obj_pos_sum, npos}
__device__ unsigned int g_done = 0;

static __device__ __forceinline__ float softplus_f(float x) {
    return fmaxf(x, 0.0f) + __logf(1.0f + __expf(-fabsf(x)));
}

// block reduce; result valid on thread 0
static __device__ __forceinline__ float blk_reduce(float v) {
    __shared__ float sh[TPB / 32];
    __syncthreads();
    #pragma unroll
    for (int o = 16; o > 0; o >>= 1) v += __shfl_down_sync(0xffffffffu, v, o);
    int lane = threadIdx.x & 31, w = threadIdx.x >> 5;
    if (lane == 0) sh[w] = v;
    __syncthreads();
    v = (threadIdx.x < TPB / 32) ? sh[threadIdx.x] : 0.0f;
    if (w == 0) {
        #pragma unroll
        for (int o = TPB / 64; o > 0; o >>= 1) v += __shfl_down_sync(0xffffffffu, v, o);
    }
    return v;
}

// fused 4-value block reduce (2 barriers); results valid on thread 0 in r[0..3]
static __device__ __forceinline__ void blk_reduce4(float v0, float v1, float v2, float v3,
                                                   float* r) {
    __shared__ float sh[TPB / 32][4];
    __syncthreads();
    #pragma unroll
    for (int o = 16; o > 0; o >>= 1) {
        v0 += __shfl_xor_sync(0xffffffffu, v0, o);
        v1 += __shfl_xor_sync(0xffffffffu, v1, o);
        v2 += __shfl_xor_sync(0xffffffffu, v2, o);
        v3 += __shfl_xor_sync(0xffffffffu, v3, o);
    }
    int lane = threadIdx.x & 31, w = threadIdx.x >> 5;
    if (lane == 0) { sh[w][0] = v0; sh[w][1] = v1; sh[w][2] = v2; sh[w][3] = v3; }
    __syncthreads();
    if (threadIdx.x == 0) {
        float a = 0.f, b = 0.f, c = 0.f, d = 0.f;
        #pragma unroll
        for (int i = 0; i < TPB / 32; i++) {
            a += sh[i][0]; b += sh[i][1]; c += sh[i][2]; d += sh[i][3];
        }
        r[0] = a; r[1] = b; r[2] = c; r[3] = d;
    }
}

__global__ __launch_bounds__(TPB)
void detloss_kernel(const float* __restrict__ cls0, const float* __restrict__ cls1,
                    const float* __restrict__ cls2,
                    const float* __restrict__ reg0, const float* __restrict__ reg1,
                    const float* __restrict__ reg2,
                    const float* __restrict__ obj0, const float* __restrict__ obj1,
                    const float* __restrict__ obj2,
                    const float* __restrict__ boxes, const int* __restrict__ labels,
                    float* __restrict__ out)
{
    const float* clsp[3] = {cls0, cls1, cls2};
    const float* regp[3] = {reg0, reg1, reg2};
    const float* objp[3] = {obj0, obj1, obj2};

    int bid = blockIdx.x;
    int t = threadIdx.x;

    if (bid < SP_BLOCKS) {
        // ---- objectness softplus sum: 2 float4 per thread ----
        const float4* src;
        int base, lim;
        if (bid < SP0_BLOCKS) {
            src = (const float4*)obj0; base = bid * 512; lim = 25600;
        } else if (bid < SP0_BLOCKS + SP1_BLOCKS) {
            src = (const float4*)obj1; base = (bid - SP0_BLOCKS) * 512; lim = 6400;
        } else {
            src = (const float4*)obj2; base = (bid - SP0_BLOCKS - SP1_BLOCKS) * 512; lim = 1600;
        }
        int i0 = base + t, i1 = base + 256 + t;
        float acc = 0.0f;
        if (i0 < lim) {
            float4 v = src[i0];
            acc += softplus_f(v.x) + softplus_f(v.y) + softplus_f(v.z) + softplus_f(v.w);
        }
        if (i1 < lim) {
            float4 v = src[i1];
            acc += softplus_f(v.x) + softplus_f(v.y) + softplus_f(v.z) + softplus_f(v.w);
        }
        float tot = blk_reduce(acc);
        if (t == 0) __stcg(&g_blk_sp[bid], tot);
    } else {
        // ---- per (scale, batch): 4 threads per box ----
        int idx = bid - SP_BLOCKS;
        int s = idx >> 4;          // 0..2
        int b = idx & 15;          // 0..15
        int Wd = 80 >> s;          // 80, 40, 20
        int HW = Wd * Wd;

        int box  = t >> 2;         // 0..63
        int part = t & 3;          // 0..3

        __shared__ int spk[NBOX];  // packed (cell<<5)|label

        // box coords + cell (all 4 parts compute identically; broadcast loads)
        const float4 bx = ((const float4*)boxes)[b * NBOX + box];
        int gx = (int)(bx.x * (float)Wd);
        int gy = (int)(bx.y * (float)Wd);
        gx = max(0, min(gx, Wd - 1));
        gy = max(0, min(gy, Wd - 1));
        int cell = gy * Wd + gx;
        int lab  = labels[b * NBOX + box];
        int mypk = (cell << 5) | lab;
        if (part == 0) spk[box] = mypk;

        // ---- speculative gathers (issued before the barrier; scattered) ----
        // classes: part p covers [8p, 8p+8) (part 3: 6 real + 2 padded)
        int cbase = part * 8;
        const float* cp = clsp[s] + (size_t)b * NCLS * HW + cell;
        float v[8];
        #pragma unroll
        for (int i = 0; i < 8; i++) {
            int c = cbase + i;
            int cc = min(c, NCLS - 1);
            float val = __ldg(&cp[(size_t)cc * HW]);
            v[i] = (c < NCLS) ? val : -1e30f;
        }
        // reg: part p loads coordinate p
        float regv = __ldg(&regp[s][(size_t)b * 4 * HW + (size_t)part * HW + cell]);
        // obj: part 3 loads it
        float objv = (part == 3) ? __ldg(&objp[s][(size_t)b * HW + cell]) : 0.0f;
        __syncthreads();

        // ---- collision resolution: split across the 4 parts (16 boxes each) ----
        int mlpk = mypk;
        int lose = 0;
        #pragma unroll
        for (int jj = 0; jj < 16; jj++) {
            int j = part * 16 + jj;
            int pj = spk[j];
            bool eq = (((pj ^ mypk) & ~31) == 0);   // same cell
            mlpk = (eq && pj < mlpk) ? pj : mlpk;    // min packed -> min label in cell
            lose |= (eq && j > box) ? 1 : 0;         // a later box overwrites this cell
        }
        // combine partials across the 4-lane group
        mlpk = min(mlpk, __shfl_xor_sync(0xffffffffu, mlpk, 1));
        mlpk = min(mlpk, __shfl_xor_sync(0xffffffffu, mlpk, 2));
        lose |= __shfl_xor_sync(0xffffffffu, lose, 1);
        lose |= __shfl_xor_sync(0xffffffffu, lose, 2);
        int ml = mlpk & 31;
        bool winner = (lose == 0);

        // ---- group-of-4 combine (contiguous lanes, same warp) ----
        float m = v[0];
        #pragma unroll
        for (int i = 1; i < 8; i++) m = fmaxf(m, v[i]);
        m = fmaxf(m, __shfl_xor_sync(0xffffffffu, m, 1));
        m = fmaxf(m, __shfl_xor_sync(0xffffffffu, m, 2));

        float ssum = 0.0f, tgt = 0.0f;
        #pragma unroll
        for (int i = 0; i < 8; i++) {
            int c = cbase + i;
            ssum += __expf(v[i] - m);                // padded entries -> exp(-huge)=0
            tgt = (c == ml) ? v[i] : tgt;
        }
        float bc = (part == 0) ? bx.x : (part == 1) ? bx.y : (part == 2) ? bx.z : bx.w;
        float d = fabsf(regv - bc);
        float sl = (d < 1.0f) ? 0.5f * d * d : d - 0.5f;

        ssum += __shfl_xor_sync(0xffffffffu, ssum, 1);
        ssum += __shfl_xor_sync(0xffffffffu, ssum, 2);
        tgt  += __shfl_xor_sync(0xffffffffu, tgt, 1);
        tgt  += __shfl_xor_sync(0xffffffffu, tgt, 2);
        sl   += __shfl_xor_sync(0xffffffffu, sl, 1);
        sl   += __shfl_xor_sync(0xffffffffu, sl, 2);

        float cls_l = 0.0f, reg_l = 0.0f, objp_l = 0.0f, np_l = 0.0f;
        if (winner) {
            if (part == 0) {
                np_l  = 1.0f;
                cls_l = m + __logf(ssum) - tgt;
                reg_l = fminf(sl * 0.25f, 10.0f);
            }
            if (part == 3) objp_l = objv;
        }
        __shared__ float res[4];
        blk_reduce4(cls_l, reg_l, objp_l, np_l, res);
        if (t == 0) {
            float4 o4 = make_float4(res[0], res[1], res[2], res[3]);
            __stcg(&g_blk_as[idx], o4);
        }
    }

    // ---- last arriving block: single acq_rel ticket ----
    __shared__ bool amLast;
    if (t == 0) {
        unsigned vv;
        asm volatile("atom.add.acq_rel.gpu.global.u32 %0, [%1], %2;"
                     : "=r"(vv) : "l"(&g_done), "r"(1u) : "memory");
        amLast = (vv == (unsigned)(gridDim.x - 1));
    }
    __syncthreads();
    if (!amLast) return;

    // ---- fast tail: single warp-parallel pass, one barrier ----
    int lane = t & 31, w = t >> 5;
    __shared__ float fin[6][4];   // [0..2]: asgn per scale {cls,reg,objp,npos}; [3..5]: sp sums {s0,s1,s2,-}

    if (w < 3) {
        // warp w reduces the 16 assignment partials of scale w
        float4 a4 = make_float4(0.f, 0.f, 0.f, 0.f);
        if (lane < NBATCH) a4 = __ldcg(&g_blk_as[w * NBATCH + lane]);
        #pragma unroll
        for (int o = 8; o > 0; o >>= 1) {
            a4.x += __shfl_xor_sync(0xffffffffu, a4.x, o);
            a4.y += __shfl_xor_sync(0xffffffffu, a4.y, o);
            a4.z += __shfl_xor_sync(0xffffffffu, a4.z, o);
            a4.w += __shfl_xor_sync(0xffffffffu, a4.w, o);
        }
        if (lane == 0) { fin[w][0] = a4.x; fin[w][1] = a4.y; fin[w][2] = a4.z; fin[w][3] = a4.w; }
    } else if (w < 6) {
        // warps 3..5 reduce the 67 softplus partials, masked into 3 per-scale sums
        int i = (w - 3) * 32 + lane;
        float pv = (i < SP_BLOCKS) ? __ldcg(&g_blk_sp[i]) : 0.0f;
        float l0 = (i < SP0_BLOCKS) ? pv : 0.0f;
        float l1 = (i >= SP0_BLOCKS && i < SP0_BLOCKS + SP1_BLOCKS) ? pv : 0.0f;
        float l2 = (i >= SP0_BLOCKS + SP1_BLOCKS && i < SP_BLOCKS) ? pv : 0.0f;
        #pragma unroll
        for (int o = 16; o > 0; o >>= 1) {
            l0 += __shfl_xor_sync(0xffffffffu, l0, o);
            l1 += __shfl_xor_sync(0xffffffffu, l1, o);
            l2 += __shfl_xor_sync(0xffffffffu, l2, o);
        }
        if (lane == 0) { fin[w][0] = l0; fin[w][1] = l1; fin[w][2] = l2; fin[w][3] = 0.0f; }
    }
    __syncthreads();

    if (t == 0) {
        float cls_tot = 0.0f, reg_tot = 0.0f, obj_tot = 0.0f;
        #pragma unroll
        for (int s = 0; s < 3; s++) {
            float sp_s = fin[3][s] + fin[4][s] + fin[5][s];
            float npos = fmaxf(fin[s][3], 1.0f);
            int Wd = 80 >> s;
            float Ms = (float)(NBATCH * Wd * Wd);
            cls_tot += fin[s][0] / npos;               // CLS_W = 1
            reg_tot += fin[s][1] / npos * 5.0f;        // REG_W = 5
            obj_tot += (sp_s - fin[s][2]) / Ms;        // OBJ_W = 1
        }
        cls_tot *= (1.0f / 3.0f);
        reg_tot *= (1.0f / 3.0f);
        obj_tot *= (1.0f / 3.0f);
        out[0] = cls_tot + reg_tot + obj_tot;
        out[1] = cls_tot;
        out[2] = reg_tot;
        out[3] = obj_tot;
        g_done = 0;   // reset for next graph replay
    }
}

extern "C" void kernel_launch(void* const* d_in, const int* in_sizes, int n_in,
                              void* d_out, int out_size)
{
    const float *cls[3], *reg[3], *obj[3];
    if (in_sizes[1] == 409600) {   // dict order: cls0,reg0,obj0,cls1,...
        cls[0] = (const float*)d_in[0]; reg[0] = (const float*)d_in[1]; obj[0] = (const float*)d_in[2];
        cls[1] = (const float*)d_in[3]; reg[1] = (const float*)d_in[4]; obj[1] = (const float*)d_in[5];
        cls[2] = (const float*)d_in[6]; reg[2] = (const float*)d_in[7]; obj[2] = (const float*)d_in[8];
    } else {                        // signature order: cls0,cls1,cls2,reg0,...
        cls[0] = (const float*)d_in[0]; cls[1] = (const float*)d_in[1]; cls[2] = (const float*)d_in[2];
        reg[0] = (const float*)d_in[3]; reg[1] = (const float*)d_in[4]; reg[2] = (const float*)d_in[5];
        obj[0] = (const float*)d_in[6]; obj[1] = (const float*)d_in[7]; obj[2] = (const float*)d_in[8];
    }
    const float* boxes  = (const float*)d_in[9];
    const int*   labels = (const int*)d_in[10];
    float* out = (float*)d_out;

    detloss_kernel<<<TOTAL_BLOCKS, TPB>>>(
        cls[0], cls[1], cls[2],
        reg[0], reg[1], reg[2],
        obj[0], obj[1], obj[2],
        boxes, labels, out);
}